// round 16
// baseline (speedup 1.0000x reference)
#include <cuda_runtime.h>
#include <cuda_fp16.h>
#include <cstdint>

#define NN 100000
#define NE 6400000
#define FIN 128
#define NB_N 391           // ceil(NN/256)
#define SLOTS 128          // bucket width (mean deg 64; P(>128) ~ 2e-6, guarded)
#define XS_STRIDE 129      // padded row stride (bank-conflict-free 4x4 tiling)
#define FB_BLOCKS 1184     // k_final: 148 SMs * 8 blocks, node-strided

// ---------------- scratch (device globals; no allocation allowed) ------------
// g_cnt invariant: zero at entry of every kernel_launch call (.bss initially;
// k_final re-zeroes it at the end of every call).
__device__ int    g_cnt[NN];              // in-degree (excl self-loop), fill cursor
__device__ float  g_dinv[NN];             // rsqrt(min(cnt,SLOTS)+1)
__device__ int    g_adj[NN * SLOTS];      // bucketed adjacency: src grouped by dst
__device__ __half g_hn1h[(NN + 1) * 16];  // (x@W1)*dinv fp16; row NN = zeros (sentinel)
__device__ float  g_agg1[NN * 16];
__device__ __half g_hn2h[(NN + 1) * 32];  // (h1@W2)*dinv fp16; row NN = zeros (sentinel)
__device__ float  g_agg2[NN * 32];

// ---------------- helpers ------------------------------------------------------
__device__ __forceinline__ void acc8_from_u4(float* acc, uint4 u) {
    __half2 h;
    h = *(__half2*)&u.x; float2 f = __half22float2(h); acc[0] += f.x; acc[1] += f.y;
    h = *(__half2*)&u.y; f = __half22float2(h); acc[2] += f.x; acc[3] += f.y;
    h = *(__half2*)&u.z; f = __half22float2(h); acc[4] += f.x; acc[5] += f.y;
    h = *(__half2*)&u.w; f = __half22float2(h); acc[6] += f.x; acc[7] += f.y;
}

// ---------------- kernels ----------------------------------------------------

// single-pass bucketed CSR fill: 4 edges per thread, vector loads.
// dtype sniff (int32 vs int64 edge layout) done per-block, broadcast via smem.
__global__ void __launch_bounds__(256) k_fill(const void* __restrict__ ei) {
    __shared__ int s_is64;
    if (threadIdx.x == 0) {
        const unsigned long long* p = (const unsigned long long*)ei;
        int is64 = 1;
        #pragma unroll
        for (int k = 0; k < 16; k++)
            if (p[k] >= (unsigned long long)NN) is64 = 0;
        s_is64 = is64;
    }
    __syncthreads();

    long long t = (long long)blockIdx.x * 256 + threadIdx.x;
    if (t * 4 >= NE) return;
    int s[4], d[4];
    if (s_is64) {
        const longlong2* p = (const longlong2*)ei;
        longlong2 a = p[t * 2], b = p[t * 2 + 1];
        s[0] = (int)a.x; s[1] = (int)a.y; s[2] = (int)b.x; s[3] = (int)b.y;
        longlong2 c = p[NE / 2 + t * 2], e = p[NE / 2 + t * 2 + 1];
        d[0] = (int)c.x; d[1] = (int)c.y; d[2] = (int)e.x; d[3] = (int)e.y;
    } else {
        const int4* p = (const int4*)ei;
        int4 a = p[t];
        s[0] = a.x; s[1] = a.y; s[2] = a.z; s[3] = a.w;
        int4 b = p[NE / 4 + t];
        d[0] = b.x; d[1] = b.y; d[2] = b.z; d[3] = b.w;
    }
    #pragma unroll
    for (int k = 0; k < 4; k++) {
        int pz = atomicAdd(&g_cnt[d[k]], 1);
        if (pz < SLOTS) g_adj[(d[k] << 7) + pz] = s[k];
    }
}

// hn1h = fp16((x @ W1) * dinv); + prep (clamp cnt, publish dinv, pad buckets).
// 128 rows/block, 128 threads; thread = (rowgrp, colgrp) computes 4x4 tile.
__global__ void __launch_bounds__(128) k_xw1(const float* __restrict__ x,
                                             const float* __restrict__ W1) {
    extern __shared__ float sm[];
    float* W1s = sm;                 // [FIN*16]
    float* xs  = sm + FIN * 16;      // [128][XS_STRIDE]
    int tid = threadIdx.x;
    for (int i = tid; i < FIN * 16; i += 128) W1s[i] = W1[i];

    int row0 = blockIdx.x * 128;
    int nrows = min(128, NN - row0);
    const float4* xsrc = (const float4*)(x + (long long)row0 * FIN);
    for (int i = tid; i < nrows * 32; i += 128) {
        int row = i >> 5, part = i & 31;
        float4 v = xsrc[row * 32 + part];
        float* dstp = xs + row * XS_STRIDE + part * 4;
        dstp[0] = v.x; dstp[1] = v.y; dstp[2] = v.z; dstp[3] = v.w;
    }

    // prep: one node per thread
    if (tid < nrows) {
        int node = row0 + tid;
        int cnt = g_cnt[node];
        if (cnt > SLOTS) { cnt = SLOTS; g_cnt[node] = SLOTS; }
        g_dinv[node] = rsqrtf((float)(cnt + 1));
        int padded = (cnt + 15) & ~15;
        for (int j = cnt; j < padded; j++) g_adj[(node << 7) + j] = NN;
    }
    __syncthreads();

    int rg = tid >> 2;          // row group (0..31)
    int cg = tid & 3;           // col group (0..3)
    int r0 = rg * 4;
    if (r0 >= nrows) return;

    float a[4][4];
    #pragma unroll
    for (int i = 0; i < 4; i++)
        #pragma unroll
        for (int j = 0; j < 4; j++) a[i][j] = 0.f;

    #pragma unroll 4
    for (int k = 0; k < FIN; k++) {
        float4 w = *(const float4*)&W1s[k * 16 + cg * 4];
        #pragma unroll
        for (int i = 0; i < 4; i++) {
            float xv = xs[(r0 + i) * XS_STRIDE + k];
            a[i][0] += xv * w.x; a[i][1] += xv * w.y;
            a[i][2] += xv * w.z; a[i][3] += xv * w.w;
        }
    }
    #pragma unroll
    for (int i = 0; i < 4; i++) {
        int row = r0 + i;
        if (row < nrows) {
            int node = row0 + row;
            float dinv = g_dinv[node];
            __half2* p = (__half2*)(g_hn1h + node * 16 + cg * 4);
            p[0] = __floats2half2_rn(a[i][0] * dinv, a[i][1] * dinv);
            p[1] = __floats2half2_rn(a[i][2] * dinv, a[i][3] * dinv);
        }
    }
}

// pull agg, 16 fp16 feats: warp/node, lanes = 16 neighbors x 2 octs (16B each)
__global__ void __launch_bounds__(256) k_agg1_pull() {
    int warp = threadIdx.x >> 5;
    int lane = threadIdx.x & 31;
    int node = blockIdx.x * 8 + warp;
    if (node >= NN) return;
    int q  = lane & 1;
    int j0 = lane >> 1;
    const int* adj = g_adj + (node << 7) + j0;
    int iters = (g_cnt[node] + 15) >> 4;

    float acc[8] = {0,0,0,0,0,0,0,0};
    if (j0 == 0) {  // self-loop
        uint4 u = ((const uint4*)g_hn1h)[node * 2 + q];
        acc8_from_u4(acc, u);
    }
    int it = 0;
    for (; it + 1 < iters; it += 2) {
        int s0 = __ldg(adj + it * 16);
        int s1 = __ldg(adj + it * 16 + 16);
        uint4 u0 = ((const uint4*)g_hn1h)[s0 * 2 + q];
        uint4 u1 = ((const uint4*)g_hn1h)[s1 * 2 + q];
        acc8_from_u4(acc, u0);
        acc8_from_u4(acc, u1);
    }
    if (it < iters) {
        int s0 = __ldg(adj + it * 16);
        uint4 u0 = ((const uint4*)g_hn1h)[s0 * 2 + q];
        acc8_from_u4(acc, u0);
    }
    #pragma unroll
    for (int m = 16; m >= 2; m >>= 1) {
        #pragma unroll
        for (int k = 0; k < 8; k++)
            acc[k] += __shfl_xor_sync(0xffffffff, acc[k], m);
    }
    if (lane < 2) {
        float d = g_dinv[node];
        float4 va = make_float4(acc[0]*d, acc[1]*d, acc[2]*d, acc[3]*d);
        float4 vb = make_float4(acc[4]*d, acc[5]*d, acc[6]*d, acc[7]*d);
        ((float4*)g_agg1)[node * 4 + q * 2]     = va;
        ((float4*)g_agg1)[node * 4 + q * 2 + 1] = vb;
    }
}

// h1 = relu(agg1 + b1); hn2h = fp16((h1 @ W2) * dinv)
// 2 threads per node: thread = (node, 16-col half). Grid = 782.
__global__ void __launch_bounds__(256) k_node12(const float* __restrict__ b1,
                                                const float* __restrict__ W2) {
    __shared__ float W2s[16 * 32];
    __shared__ float b1s[16];
    int tid = threadIdx.x;
    for (int i = tid; i < 512; i += 256) W2s[i] = W2[i];
    if (tid < 16) b1s[tid] = b1[tid];
    __syncthreads();

    int idx = blockIdx.x * 256 + tid;
    if (idx >= NN * 2) return;
    int node = idx >> 1;
    int half = idx & 1;

    float h[16];
    const float4* a4 = (const float4*)(g_agg1 + node * 16);
    #pragma unroll
    for (int j = 0; j < 4; j++) {
        float4 v = a4[j];
        h[j * 4 + 0] = v.x; h[j * 4 + 1] = v.y; h[j * 4 + 2] = v.z; h[j * 4 + 3] = v.w;
    }
    #pragma unroll
    for (int k = 0; k < 16; k++) h[k] = fmaxf(h[k] + b1s[k], 0.f);

    float d = g_dinv[node];
    int c0 = half * 16;
    __half2* outp = (__half2*)(g_hn2h + node * 32 + c0);
    #pragma unroll 2
    for (int c = 0; c < 16; c += 2) {
        float s0 = 0.f, s1 = 0.f;
        #pragma unroll
        for (int k = 0; k < 16; k++) {
            s0 += h[k] * W2s[k * 32 + c0 + c];
            s1 += h[k] * W2s[k * 32 + c0 + c + 1];
        }
        outp[c >> 1] = __floats2half2_rn(s0 * d, s1 * d);
    }
}

// pull agg, 32 fp16 feats: warp/node, lanes = 8 neighbors x 4 octs (16B each)
__global__ void __launch_bounds__(256) k_agg2_pull() {
    int warp = threadIdx.x >> 5;
    int lane = threadIdx.x & 31;
    int node = blockIdx.x * 8 + warp;
    if (node >= NN) return;
    int q  = lane & 3;
    int j0 = lane >> 2;
    const int* adj = g_adj + (node << 7) + j0;
    int iters = (g_cnt[node] + 7) >> 3;    // pad-to-16 covers stride 8

    float acc[8] = {0,0,0,0,0,0,0,0};
    if (j0 == 0) {  // self-loop
        uint4 u = ((const uint4*)g_hn2h)[node * 4 + q];
        acc8_from_u4(acc, u);
    }
    int it = 0;
    for (; it + 1 < iters; it += 2) {
        int s0 = __ldg(adj + it * 8);
        int s1 = __ldg(adj + it * 8 + 8);
        uint4 u0 = ((const uint4*)g_hn2h)[s0 * 4 + q];
        uint4 u1 = ((const uint4*)g_hn2h)[s1 * 4 + q];
        acc8_from_u4(acc, u0);
        acc8_from_u4(acc, u1);
    }
    if (it < iters) {
        int s0 = __ldg(adj + it * 8);
        uint4 u0 = ((const uint4*)g_hn2h)[s0 * 4 + q];
        acc8_from_u4(acc, u0);
    }
    #pragma unroll
    for (int m = 16; m >= 4; m >>= 1) {
        #pragma unroll
        for (int k = 0; k < 8; k++)
            acc[k] += __shfl_xor_sync(0xffffffff, acc[k], m);
    }
    if (lane < 4) {
        float d = g_dinv[node];
        float4 va = make_float4(acc[0]*d, acc[1]*d, acc[2]*d, acc[3]*d);
        float4 vb = make_float4(acc[4]*d, acc[5]*d, acc[6]*d, acc[7]*d);
        ((float4*)g_agg2)[node * 8 + q * 2]     = va;
        ((float4*)g_agg2)[node * 8 + q * 2 + 1] = vb;
    }
}

// h2 = relu(agg2 + b2); out = MLP 32->64->32->16; re-zero g_cnt.
// Warp-per-node, node-strided over FB_BLOCKS blocks. Lanes <-> feature/hidden
// units; staging through smem (low regs, high occupancy). Weights loaded once
// per block (1184 blocks -> 5.4MB weight traffic).
__global__ void __launch_bounds__(256) k_final(const float* __restrict__ b2,
                                               const float* __restrict__ Wf1,
                                               const float* __restrict__ bf1,
                                               const float* __restrict__ Wf2,
                                               const float* __restrict__ bf2,
                                               const float* __restrict__ Wf3,
                                               const float* __restrict__ bf3,
                                               float* __restrict__ out) {
    __shared__ float s_wf1[32 * 64];
    __shared__ float s_wf2[64 * 32];
    __shared__ float s_wf3[32 * 16];
    __shared__ float s_b2[32], s_bf1[64], s_bf2[32], s_bf3[16];
    __shared__ float sh2[8][32];
    __shared__ float st1[8][64];
    __shared__ float st2[8][32];
    int tid = threadIdx.x;
    for (int i = tid; i < 2048; i += 256) s_wf1[i] = Wf1[i];
    for (int i = tid; i < 2048; i += 256) s_wf2[i] = Wf2[i];
    for (int i = tid; i < 512;  i += 256) s_wf3[i] = Wf3[i];
    if (tid < 64) s_bf1[tid] = bf1[tid];
    if (tid < 32) { s_b2[tid] = b2[tid]; s_bf2[tid] = bf2[tid]; }
    if (tid < 16) s_bf3[tid] = bf3[tid];

    // restore g_cnt invariant for next call (grid-strided)
    for (int i = blockIdx.x * 256 + tid; i < NN; i += FB_BLOCKS * 256)
        g_cnt[i] = 0;
    __syncthreads();

    int warp = tid >> 5;
    int lane = tid & 31;

    for (int node = blockIdx.x * 8 + warp; node < NN; node += FB_BLOCKS * 8) {
        // h2 = relu(agg2 + b2): lane k holds feature k (coalesced 128B row)
        float h = fmaxf(g_agg2[node * 32 + lane] + s_b2[lane], 0.f);
        sh2[warp][lane] = h;
        __syncwarp();

        // t1 = relu(h2 @ Wf1 + bf1): 2 hidden units per lane (smem broadcast)
        float u0 = s_bf1[lane], u1 = s_bf1[lane + 32];
        #pragma unroll 8
        for (int k = 0; k < 32; k++) {
            float hk = sh2[warp][k];
            u0 += hk * s_wf1[k * 64 + lane];
            u1 += hk * s_wf1[k * 64 + lane + 32];
        }
        st1[warp][lane]      = fmaxf(u0, 0.f);
        st1[warp][lane + 32] = fmaxf(u1, 0.f);
        __syncwarp();

        // t2 = relu(t1 @ Wf2 + bf2): 1 unit per lane
        float t = s_bf2[lane];
        #pragma unroll 8
        for (int j = 0; j < 64; j++) t += st1[warp][j] * s_wf2[j * 32 + lane];
        st2[warp][lane] = fmaxf(t, 0.f);
        __syncwarp();

        // out = t2 @ Wf3 + bf3: lanes 0..15
        if (lane < 16) {
            float o = s_bf3[lane];
            #pragma unroll
            for (int k = 0; k < 32; k++) o += st2[warp][k] * s_wf3[k * 16 + lane];
            out[node * 16 + lane] = o;
        }
        __syncwarp();
    }
}

// ---------------- launch ------------------------------------------------------
extern "C" void kernel_launch(void* const* d_in, const int* in_sizes, int n_in,
                              void* d_out, int out_size) {
    const float* x   = (const float*)d_in[0];
    const float* W1  = (const float*)d_in[1];
    const float* b1  = (const float*)d_in[2];
    const float* W2  = (const float*)d_in[3];
    const float* b2  = (const float*)d_in[4];
    const float* Wf1 = (const float*)d_in[5];
    const float* bf1 = (const float*)d_in[6];
    const float* Wf2 = (const float*)d_in[7];
    const float* bf2 = (const float*)d_in[8];
    const float* Wf3 = (const float*)d_in[9];
    const float* bf3 = (const float*)d_in[10];
    const void*  ei  = d_in[11];
    float* out = (float*)d_out;

    const int XW1_SMEM = (FIN * 16 + 128 * XS_STRIDE) * 4;  // 74,240 B
    static bool attr_set = false;
    if (!attr_set) {
        cudaFuncSetAttribute(k_xw1, cudaFuncAttributeMaxDynamicSharedMemorySize,
                             XW1_SMEM);
        attr_set = true;
    }

    const int NB_F = (NE / 4 + 255) / 256;      // 6250 (4 edges/thread)
    const int NB_X = (NN + 127) / 128;          // 782
    const int NB_W = (NN + 7) / 8;              // 12500 (warp per node)
    const int NB_2 = (NN * 2 + 255) / 256;      // 782  (2 threads/node)

    k_fill<<<NB_F, 256>>>(ei);                                     // 1
    k_xw1<<<NB_X, 128, XW1_SMEM>>>(x, W1);                         // 2
    k_agg1_pull<<<NB_W, 256>>>();                                  // 3
    k_node12<<<NB_2, 256>>>(b1, W2);                               // 4 <- profiled slot
    k_agg2_pull<<<NB_W, 256>>>();                                  // 5
    k_final<<<FB_BLOCKS, 256>>>(b2, Wf1, bf1, Wf2, bf2, Wf3, bf3, out); // 6
}

// round 17
// speedup vs baseline: 1.1577x; 1.1577x over previous
#include <cuda_runtime.h>
#include <cuda_fp16.h>
#include <cstdint>

#define NN 100000
#define NE 6400000
#define FIN 128
#define NB_N 391           // ceil(NN/256)
#define SLOTS 128          // bucket width (mean deg 64; P(>128) ~ 2e-6, guarded)
#define XS_STRIDE 129      // padded row stride (bank-conflict-free 4x4 tiling)

// ---------------- scratch (device globals; no allocation allowed) ------------
// g_cnt invariant: zero at entry of every kernel_launch call (.bss initially;
// k_final re-zeroes it at the end of every call).
__device__ int    g_cnt[NN];              // in-degree (excl self-loop), fill cursor
__device__ float  g_dinv[NN];             // rsqrt(min(cnt,SLOTS)+1)
__device__ int    g_adj[NN * SLOTS];      // bucketed adjacency: src grouped by dst
__device__ __half g_hn1h[(NN + 1) * 16];  // (x@W1)*dinv fp16; row NN = zeros (sentinel)
__device__ float  g_agg1[NN * 16];
__device__ __half g_hn2h[(NN + 1) * 32];  // (h1@W2)*dinv fp16; row NN = zeros (sentinel)
__device__ float  g_agg2[NN * 32];

// ---------------- helpers ------------------------------------------------------
__device__ __forceinline__ void acc8_from_u4(float* acc, uint4 u) {
    __half2 h;
    h = *(__half2*)&u.x; float2 f = __half22float2(h); acc[0] += f.x; acc[1] += f.y;
    h = *(__half2*)&u.y; f = __half22float2(h); acc[2] += f.x; acc[3] += f.y;
    h = *(__half2*)&u.z; f = __half22float2(h); acc[4] += f.x; acc[5] += f.y;
    h = *(__half2*)&u.w; f = __half22float2(h); acc[6] += f.x; acc[7] += f.y;
}

// ---------------- kernels ----------------------------------------------------

// single-pass bucketed CSR fill: 4 edges per thread, vector loads.
// dtype sniff (int32 vs int64 edge layout) done per-block, broadcast via smem.
__global__ void __launch_bounds__(256) k_fill(const void* __restrict__ ei) {
    __shared__ int s_is64;
    if (threadIdx.x == 0) {
        const unsigned long long* p = (const unsigned long long*)ei;
        int is64 = 1;
        #pragma unroll
        for (int k = 0; k < 16; k++)
            if (p[k] >= (unsigned long long)NN) is64 = 0;
        s_is64 = is64;
    }
    __syncthreads();

    long long t = (long long)blockIdx.x * 256 + threadIdx.x;
    if (t * 4 >= NE) return;
    int s[4], d[4];
    if (s_is64) {
        const longlong2* p = (const longlong2*)ei;
        longlong2 a = p[t * 2], b = p[t * 2 + 1];
        s[0] = (int)a.x; s[1] = (int)a.y; s[2] = (int)b.x; s[3] = (int)b.y;
        longlong2 c = p[NE / 2 + t * 2], e = p[NE / 2 + t * 2 + 1];
        d[0] = (int)c.x; d[1] = (int)c.y; d[2] = (int)e.x; d[3] = (int)e.y;
    } else {
        const int4* p = (const int4*)ei;
        int4 a = p[t];
        s[0] = a.x; s[1] = a.y; s[2] = a.z; s[3] = a.w;
        int4 b = p[NE / 4 + t];
        d[0] = b.x; d[1] = b.y; d[2] = b.z; d[3] = b.w;
    }
    #pragma unroll
    for (int k = 0; k < 4; k++) {
        int pz = atomicAdd(&g_cnt[d[k]], 1);
        if (pz < SLOTS) g_adj[(d[k] << 7) + pz] = s[k];
    }
}

// hn1h = fp16((x @ W1) * dinv); + prep (clamp cnt, publish dinv, pad buckets).
// 128 rows/block, 128 threads; thread = (rowgrp, colgrp) computes 4x4 tile.
__global__ void __launch_bounds__(128) k_xw1(const float* __restrict__ x,
                                             const float* __restrict__ W1) {
    extern __shared__ float sm[];
    float* W1s = sm;                 // [FIN*16]
    float* xs  = sm + FIN * 16;      // [128][XS_STRIDE]
    int tid = threadIdx.x;
    for (int i = tid; i < FIN * 16; i += 128) W1s[i] = W1[i];

    int row0 = blockIdx.x * 128;
    int nrows = min(128, NN - row0);
    const float4* xsrc = (const float4*)(x + (long long)row0 * FIN);
    for (int i = tid; i < nrows * 32; i += 128) {
        int row = i >> 5, part = i & 31;
        float4 v = xsrc[row * 32 + part];
        float* dstp = xs + row * XS_STRIDE + part * 4;
        dstp[0] = v.x; dstp[1] = v.y; dstp[2] = v.z; dstp[3] = v.w;
    }

    // prep: one node per thread
    if (tid < nrows) {
        int node = row0 + tid;
        int cnt = g_cnt[node];
        if (cnt > SLOTS) { cnt = SLOTS; g_cnt[node] = SLOTS; }
        g_dinv[node] = rsqrtf((float)(cnt + 1));
        int padded = (cnt + 15) & ~15;
        for (int j = cnt; j < padded; j++) g_adj[(node << 7) + j] = NN;
    }
    __syncthreads();

    int rg = tid >> 2;          // row group (0..31)
    int cg = tid & 3;           // col group (0..3)
    int r0 = rg * 4;
    if (r0 >= nrows) return;

    float a[4][4];
    #pragma unroll
    for (int i = 0; i < 4; i++)
        #pragma unroll
        for (int j = 0; j < 4; j++) a[i][j] = 0.f;

    #pragma unroll 4
    for (int k = 0; k < FIN; k++) {
        float4 w = *(const float4*)&W1s[k * 16 + cg * 4];
        #pragma unroll
        for (int i = 0; i < 4; i++) {
            float xv = xs[(r0 + i) * XS_STRIDE + k];
            a[i][0] += xv * w.x; a[i][1] += xv * w.y;
            a[i][2] += xv * w.z; a[i][3] += xv * w.w;
        }
    }
    #pragma unroll
    for (int i = 0; i < 4; i++) {
        int row = r0 + i;
        if (row < nrows) {
            int node = row0 + row;
            float dinv = g_dinv[node];
            __half2* p = (__half2*)(g_hn1h + node * 16 + cg * 4);
            p[0] = __floats2half2_rn(a[i][0] * dinv, a[i][1] * dinv);
            p[1] = __floats2half2_rn(a[i][2] * dinv, a[i][3] * dinv);
        }
    }
}

// pull agg, 16 fp16 feats: warp/node, lanes = 16 neighbors x 2 octs (16B each)
__global__ void __launch_bounds__(256) k_agg1_pull() {
    int warp = threadIdx.x >> 5;
    int lane = threadIdx.x & 31;
    int node = blockIdx.x * 8 + warp;
    if (node >= NN) return;
    int q  = lane & 1;
    int j0 = lane >> 1;
    const int* adj = g_adj + (node << 7) + j0;
    int iters = (g_cnt[node] + 15) >> 4;

    float acc[8] = {0,0,0,0,0,0,0,0};
    if (j0 == 0) {  // self-loop
        uint4 u = ((const uint4*)g_hn1h)[node * 2 + q];
        acc8_from_u4(acc, u);
    }
    int it = 0;
    for (; it + 1 < iters; it += 2) {
        int s0 = __ldg(adj + it * 16);
        int s1 = __ldg(adj + it * 16 + 16);
        uint4 u0 = ((const uint4*)g_hn1h)[s0 * 2 + q];
        uint4 u1 = ((const uint4*)g_hn1h)[s1 * 2 + q];
        acc8_from_u4(acc, u0);
        acc8_from_u4(acc, u1);
    }
    if (it < iters) {
        int s0 = __ldg(adj + it * 16);
        uint4 u0 = ((const uint4*)g_hn1h)[s0 * 2 + q];
        acc8_from_u4(acc, u0);
    }
    #pragma unroll
    for (int m = 16; m >= 2; m >>= 1) {
        #pragma unroll
        for (int k = 0; k < 8; k++)
            acc[k] += __shfl_xor_sync(0xffffffff, acc[k], m);
    }
    if (lane < 2) {
        float d = g_dinv[node];
        float4 va = make_float4(acc[0]*d, acc[1]*d, acc[2]*d, acc[3]*d);
        float4 vb = make_float4(acc[4]*d, acc[5]*d, acc[6]*d, acc[7]*d);
        ((float4*)g_agg1)[node * 4 + q * 2]     = va;
        ((float4*)g_agg1)[node * 4 + q * 2 + 1] = vb;
    }
}

// h1 = relu(agg1 + b1); hn2h = fp16((h1 @ W2) * dinv)
// 2 threads per node: thread = (node, 16-col half). Grid = 782.
// (measured 11.1us vs 13.1us for the 1-thread/node version)
__global__ void __launch_bounds__(256) k_node12(const float* __restrict__ b1,
                                                const float* __restrict__ W2) {
    __shared__ float W2s[16 * 32];
    __shared__ float b1s[16];
    int tid = threadIdx.x;
    for (int i = tid; i < 512; i += 256) W2s[i] = W2[i];
    if (tid < 16) b1s[tid] = b1[tid];
    __syncthreads();

    int idx = blockIdx.x * 256 + tid;
    if (idx >= NN * 2) return;
    int node = idx >> 1;
    int half = idx & 1;

    float h[16];
    const float4* a4 = (const float4*)(g_agg1 + node * 16);
    #pragma unroll
    for (int j = 0; j < 4; j++) {
        float4 v = a4[j];
        h[j * 4 + 0] = v.x; h[j * 4 + 1] = v.y; h[j * 4 + 2] = v.z; h[j * 4 + 3] = v.w;
    }
    #pragma unroll
    for (int k = 0; k < 16; k++) h[k] = fmaxf(h[k] + b1s[k], 0.f);

    float d = g_dinv[node];
    int c0 = half * 16;
    __half2* outp = (__half2*)(g_hn2h + node * 32 + c0);
    #pragma unroll 2
    for (int c = 0; c < 16; c += 2) {
        float s0 = 0.f, s1 = 0.f;
        #pragma unroll
        for (int k = 0; k < 16; k++) {
            s0 += h[k] * W2s[k * 32 + c0 + c];
            s1 += h[k] * W2s[k * 32 + c0 + c + 1];
        }
        outp[c >> 1] = __floats2half2_rn(s0 * d, s1 * d);
    }
}

// pull agg, 32 fp16 feats: warp/node, lanes = 8 neighbors x 4 octs (16B each)
__global__ void __launch_bounds__(256) k_agg2_pull() {
    int warp = threadIdx.x >> 5;
    int lane = threadIdx.x & 31;
    int node = blockIdx.x * 8 + warp;
    if (node >= NN) return;
    int q  = lane & 3;
    int j0 = lane >> 2;
    const int* adj = g_adj + (node << 7) + j0;
    int iters = (g_cnt[node] + 7) >> 3;    // pad-to-16 covers stride 8

    float acc[8] = {0,0,0,0,0,0,0,0};
    if (j0 == 0) {  // self-loop
        uint4 u = ((const uint4*)g_hn2h)[node * 4 + q];
        acc8_from_u4(acc, u);
    }
    int it = 0;
    for (; it + 1 < iters; it += 2) {
        int s0 = __ldg(adj + it * 8);
        int s1 = __ldg(adj + it * 8 + 8);
        uint4 u0 = ((const uint4*)g_hn2h)[s0 * 4 + q];
        uint4 u1 = ((const uint4*)g_hn2h)[s1 * 4 + q];
        acc8_from_u4(acc, u0);
        acc8_from_u4(acc, u1);
    }
    if (it < iters) {
        int s0 = __ldg(adj + it * 8);
        uint4 u0 = ((const uint4*)g_hn2h)[s0 * 4 + q];
        acc8_from_u4(acc, u0);
    }
    #pragma unroll
    for (int m = 16; m >= 4; m >>= 1) {
        #pragma unroll
        for (int k = 0; k < 8; k++)
            acc[k] += __shfl_xor_sync(0xffffffff, acc[k], m);
    }
    if (lane < 4) {
        float d = g_dinv[node];
        float4 va = make_float4(acc[0]*d, acc[1]*d, acc[2]*d, acc[3]*d);
        float4 vb = make_float4(acc[4]*d, acc[5]*d, acc[6]*d, acc[7]*d);
        ((float4*)g_agg2)[node * 8 + q * 2]     = va;
        ((float4*)g_agg2)[node * 8 + q * 2 + 1] = vb;
    }
}

// h2 = relu(agg2 + b2); out = MLP(h2): 32 -> 64 -> 32 -> 16; re-zero g_cnt
// (register-resident 1-thread/node version — measured best)
__global__ void __launch_bounds__(256) k_final(const float* __restrict__ b2,
                                               const float* __restrict__ Wf1,
                                               const float* __restrict__ bf1,
                                               const float* __restrict__ Wf2,
                                               const float* __restrict__ bf2,
                                               const float* __restrict__ Wf3,
                                               const float* __restrict__ bf3,
                                               float* __restrict__ out) {
    __shared__ float s_wf1[32 * 64];
    __shared__ float s_wf2[64 * 32];
    __shared__ float s_wf3[32 * 16];
    __shared__ float s_b2[32], s_bf1[64], s_bf2[32], s_bf3[16];
    int tid = threadIdx.x;
    for (int i = tid; i < 2048; i += 256) s_wf1[i] = Wf1[i];
    for (int i = tid; i < 2048; i += 256) s_wf2[i] = Wf2[i];
    for (int i = tid; i < 512;  i += 256) s_wf3[i] = Wf3[i];
    if (tid < 64) s_bf1[tid] = bf1[tid];
    if (tid < 32) { s_b2[tid] = b2[tid]; s_bf2[tid] = bf2[tid]; }
    if (tid < 16) s_bf3[tid] = bf3[tid];

    int node = blockIdx.x * 256 + tid;
    if (node < NN) g_cnt[node] = 0;   // restore invariant for next call
    __syncthreads();
    if (node >= NN) return;

    float h[32];
    const float4* a4 = (const float4*)(g_agg2 + node * 32);
    #pragma unroll
    for (int j = 0; j < 8; j++) {
        float4 v = a4[j];
        h[j * 4 + 0] = v.x; h[j * 4 + 1] = v.y; h[j * 4 + 2] = v.z; h[j * 4 + 3] = v.w;
    }
    #pragma unroll
    for (int k = 0; k < 32; k++) h[k] = fmaxf(h[k] + s_b2[k], 0.f);

    float t2[32];
    #pragma unroll
    for (int k = 0; k < 32; k++) t2[k] = s_bf2[k];

    #pragma unroll 2
    for (int j = 0; j < 64; j++) {
        float u = s_bf1[j];
        #pragma unroll
        for (int k = 0; k < 32; k++) u += h[k] * s_wf1[k * 64 + j];
        u = fmaxf(u, 0.f);
        #pragma unroll
        for (int k = 0; k < 32; k++) t2[k] += u * s_wf2[j * 32 + k];
    }
    #pragma unroll
    for (int k = 0; k < 32; k++) t2[k] = fmaxf(t2[k], 0.f);

    #pragma unroll
    for (int c = 0; c < 16; c++) {
        float o = s_bf3[c];
        #pragma unroll
        for (int k = 0; k < 32; k++) o += t2[k] * s_wf3[k * 16 + c];
        out[node * 16 + c] = o;
    }
}

// ---------------- launch ------------------------------------------------------
extern "C" void kernel_launch(void* const* d_in, const int* in_sizes, int n_in,
                              void* d_out, int out_size) {
    const float* x   = (const float*)d_in[0];
    const float* W1  = (const float*)d_in[1];
    const float* b1  = (const float*)d_in[2];
    const float* W2  = (const float*)d_in[3];
    const float* b2  = (const float*)d_in[4];
    const float* Wf1 = (const float*)d_in[5];
    const float* bf1 = (const float*)d_in[6];
    const float* Wf2 = (const float*)d_in[7];
    const float* bf2 = (const float*)d_in[8];
    const float* Wf3 = (const float*)d_in[9];
    const float* bf3 = (const float*)d_in[10];
    const void*  ei  = d_in[11];
    float* out = (float*)d_out;

    const int XW1_SMEM = (FIN * 16 + 128 * XS_STRIDE) * 4;  // 74,240 B
    static bool attr_set = false;
    if (!attr_set) {
        cudaFuncSetAttribute(k_xw1, cudaFuncAttributeMaxDynamicSharedMemorySize,
                             XW1_SMEM);
        attr_set = true;
    }

    const int NB_F = (NE / 4 + 255) / 256;      // 6250 (4 edges/thread)
    const int NB_X = (NN + 127) / 128;          // 782
    const int NB_W = (NN + 7) / 8;              // 12500 (warp per node)
    const int NB_2 = (NN * 2 + 255) / 256;      // 782  (2 threads/node)

    k_fill<<<NB_F, 256>>>(ei);                                     // 1
    k_xw1<<<NB_X, 128, XW1_SMEM>>>(x, W1);                         // 2
    k_agg1_pull<<<NB_W, 256>>>();                                  // 3
    k_node12<<<NB_2, 256>>>(b1, W2);                               // 4 <- profiled slot
    k_agg2_pull<<<NB_W, 256>>>();                                  // 5
    k_final<<<NB_N, 256>>>(b2, Wf1, bf1, Wf2, bf2, Wf3, bf3, out); // 6
}